// round 15
// baseline (speedup 1.0000x reference)
#include <cuda_runtime.h>
#include <cuda_bf16.h>
#include <cstdint>

#define BATCH 2
#define LQS 2048
#define LKS 2048
#define DM 1024
#define NHEAD 16
#define DKH 64

// ------------------------------------------------------------------
// Scratch (device globals; no cudaMalloc allowed)
// ------------------------------------------------------------------
__device__ __nv_bfloat16 g_qb[BATCH * LQS * DM];
__device__ __nv_bfloat16 g_kb[BATCH * LKS * DM];
__device__ __nv_bfloat16 g_vb[BATCH * LKS * DM];
__device__ __nv_bfloat16 g_wqb[DM * DM];
__device__ __nv_bfloat16 g_wkb[DM * DM];
__device__ __nv_bfloat16 g_wvb[DM * DM];
__device__ __nv_bfloat16 g_wfb[DM * DM];
__device__ __nv_bfloat16 g_Qp[BATCH * LQS * DM];
__device__ __nv_bfloat16 g_Kp[BATCH * LKS * DM];
__device__ __nv_bfloat16 g_Vp[BATCH * LKS * DM];
__device__ __nv_bfloat16 g_attn[BATCH * LQS * DM];
__device__ float g_fc[BATCH * LQS * DM];
__device__ uint32_t g_mb[BATCH * LQS * (LKS / 32)];
__device__ float g_meC[BATCH * LKS];
__device__ float g_sdC[BATCH * LKS];

// ------------------------------------------------------------------
// PTX helpers
// ------------------------------------------------------------------
__device__ __forceinline__ void mma_bf16(float* c, const uint32_t* a, uint32_t b0, uint32_t b1) {
    asm volatile(
        "mma.sync.aligned.m16n8k16.row.col.f32.bf16.bf16.f32 "
        "{%0,%1,%2,%3}, {%4,%5,%6,%7}, {%8,%9}, {%0,%1,%2,%3};"
        : "+f"(c[0]), "+f"(c[1]), "+f"(c[2]), "+f"(c[3])
        : "r"(a[0]), "r"(a[1]), "r"(a[2]), "r"(a[3]), "r"(b0), "r"(b1));
}
__device__ __forceinline__ void ldsm_x4(uint32_t* r, uint32_t addr) {
    asm volatile(
        "ldmatrix.sync.aligned.m8n8.x4.shared.b16 {%0,%1,%2,%3}, [%4];"
        : "=r"(r[0]), "=r"(r[1]), "=r"(r[2]), "=r"(r[3]) : "r"(addr));
}
__device__ __forceinline__ void ldsm_x4_t(uint32_t* r, uint32_t addr) {
    asm volatile(
        "ldmatrix.sync.aligned.m8n8.x4.trans.shared.b16 {%0,%1,%2,%3}, [%4];"
        : "=r"(r[0]), "=r"(r[1]), "=r"(r[2]), "=r"(r[3]) : "r"(addr));
}

#define CP_ASYNC16(dst, src) \
    asm volatile("cp.async.cg.shared.global [%0], [%1], 16;" :: "r"(dst), "l"(src))
#define CP_COMMIT() asm volatile("cp.async.commit_group;" ::: "memory")
#define CP_WAIT3() asm volatile("cp.async.wait_group 3;" ::: "memory")
#define CP_WAIT1() asm volatile("cp.async.wait_group 1;" ::: "memory")
#define CP_WAIT0() asm volatile("cp.async.wait_group 0;" ::: "memory")

__device__ __forceinline__ uint32_t smem_u32(const void* p) {
    uint32_t a;
    asm("{ .reg .u64 t; cvta.to.shared.u64 t, %1; cvt.u32.u64 %0, t; }" : "=r"(a) : "l"(p));
    return a;
}
__device__ __forceinline__ uint32_t pack_bf2(float lo, float hi) {
    __nv_bfloat162 h = __floats2bfloat162_rn(lo, hi);
    return *(uint32_t*)&h;
}

// exp2 via MUFU.
__device__ __forceinline__ float ex2f(float y) {
    float r;
    asm("ex2.approx.f32 %0, %1;" : "=f"(r) : "f"(y));
    return r;
}

// ------------------------------------------------------------------
// Fused prep: 7 fp32->bf16 conversions + mean/std pre-scaling + mask pack
// ------------------------------------------------------------------
#define NIN4 ((BATCH * LQS * DM) / 4)   // 2^20
#define NW4 ((DM * DM) / 4)             // 2^18
struct PrepArgs {
    const float4* src[7];
    uint2* dst[7];
};

__global__ __launch_bounds__(256) void prep(
    PrepArgs pa, const float* __restrict__ mean, const float* __restrict__ stdv,
    float* __restrict__ meC, float* __restrict__ sdC,
    const int* __restrict__ mask, uint32_t* __restrict__ mb)
{
    const int TOT = 3 * NIN4 + 4 * NW4;
    const int stride = gridDim.x * blockDim.x;
    for (int i = blockIdx.x * blockDim.x + threadIdx.x; i < TOT; i += stride) {
        int seg, off;
        if (i < 3 * NIN4) { seg = i >> 20; off = i & (NIN4 - 1); }
        else { int j = i - 3 * NIN4; seg = 3 + (j >> 18); off = j & (NW4 - 1); }
        float4 v = pa.src[seg][off];
        uint2 u;
        u.x = pack_bf2(v.x, v.y);
        u.y = pack_bf2(v.z, v.w);
        pa.dst[seg][off] = u;
    }
    const float CAFF = 0.18033688011f;  // 0.125 * log2(e)
    for (int i = blockIdx.x * blockDim.x + threadIdx.x; i < BATCH * LKS; i += stride) {
        meC[i] = mean[i] * CAFF;
        sdC[i] = stdv[i] * CAFF;
    }
    const int nwords = BATCH * LQS * (LKS / 32);
    int warp = (blockIdx.x * blockDim.x + threadIdx.x) >> 5;
    int lane = threadIdx.x & 31;
    int wstep = stride >> 5;
    for (int w = warp; w < nwords; w += wstep) {
        int v = mask[(size_t)w * 32 + lane];
        uint32_t bits = __ballot_sync(0xffffffffu, v != 0);
        if (lane == 0) mb[w] = bits;
    }
}

// ------------------------------------------------------------------
// bf16 GEMM via mma.m16n8k16: CTA tile 64x128, 8 warps (2x4),
// warp tile 32x32, 5-stage cp.async, 3 CTAs/SM.
// ------------------------------------------------------------------
#define GBM 64
#define GBN 128
#define GBK 32
#define GK 1024
#define GN 1024
#define A_LDB 80
#define B_LDB 272
#define ASTG_B (GBM * A_LDB)     // 5120
#define BSTG_B (GBK * B_LDB)     // 8704
#define STG_B (ASTG_B + BSTG_B)  // 13824
#define NSTAGE 5
#define GSMEM (NSTAGE * STG_B)   // 69120
#define GNITER (GK / GBK)

__device__ __forceinline__ void g_load_stage(
    uint32_t smb, int s, const __nv_bfloat16* __restrict__ A,
    const __nv_bfloat16* __restrict__ W, int m0, int n0, int kc0, int tid)
{
    uint32_t as = smb + s * STG_B;
    uint32_t bs = as + ASTG_B;
    {
        int row = tid >> 2, c = tid & 3;
        CP_ASYNC16(as + row * A_LDB + c * 16,
                   A + (size_t)(m0 + row) * GK + kc0 + c * 8);
    }
#pragma unroll
    for (int r = 0; r < 2; r++) {
        int idx = tid + r * 256;
        int row = idx >> 4, c = idx & 15;
        CP_ASYNC16(bs + row * B_LDB + c * 16,
                   W + (size_t)(kc0 + row) * GN + n0 + c * 8);
    }
}

template <bool RES, bool BF16OUT>
__device__ __forceinline__ void gemm_body(
    const __nv_bfloat16* __restrict__ A, const __nv_bfloat16* __restrict__ W,
    const float* __restrict__ Rsd, void* __restrict__ Cv, uint32_t smb)
{
    const int tid = threadIdx.x;
    const int wid = tid >> 5, lane = tid & 31;
    const int g = lane >> 2, tg = lane & 3;
    const int wm = (wid >> 2) * 32, wn = (wid & 3) * 32;
    const int m0 = blockIdx.y * GBM, n0 = blockIdx.x * GBN;

    const int jr = lane & 7, jt = lane >> 3;
    const uint32_t aoff = (uint32_t)(((jt & 1) * 8 + jr) * A_LDB + (jt >> 1) * 16);
    const uint32_t boff = (uint32_t)(((jt & 1) * 8 + jr) * B_LDB + (jt >> 1) * 16);

    float acc[2][4][4];
#pragma unroll
    for (int mt = 0; mt < 2; mt++)
#pragma unroll
        for (int nt = 0; nt < 4; nt++)
#pragma unroll
            for (int r = 0; r < 4; r++) acc[mt][nt][r] = 0.f;

#pragma unroll
    for (int s = 0; s < 4; s++) {
        g_load_stage(smb, s, A, W, m0, n0, s * GBK, tid);
        CP_COMMIT();
    }

    int st = 0;
    for (int i = 0; i < GNITER; i++) {
        CP_WAIT3();
        __syncthreads();
        if (i + 4 < GNITER) {
            int ps = st + 4; if (ps >= NSTAGE) ps -= NSTAGE;
            g_load_stage(smb, ps, A, W, m0, n0, (i + 4) * GBK, tid);
        }
        CP_COMMIT();

        const uint32_t aSt = smb + st * STG_B + wm * A_LDB + aoff;
        const uint32_t bSt = smb + st * STG_B + ASTG_B + wn * 2 + boff;

#pragma unroll
        for (int ks = 0; ks < 2; ks++) {
            uint32_t af[2][4], bv[2][4];
#pragma unroll
            for (int mt = 0; mt < 2; mt++)
                ldsm_x4(af[mt], aSt + mt * (16 * A_LDB) + ks * 32);
#pragma unroll
            for (int nh = 0; nh < 2; nh++)
                ldsm_x4_t(bv[nh], bSt + ks * (16 * B_LDB) + nh * 32);
#pragma unroll
            for (int mt = 0; mt < 2; mt++) {
                mma_bf16(acc[mt][0], af[mt], bv[0][0], bv[0][1]);
                mma_bf16(acc[mt][1], af[mt], bv[0][2], bv[0][3]);
                mma_bf16(acc[mt][2], af[mt], bv[1][0], bv[1][1]);
                mma_bf16(acc[mt][3], af[mt], bv[1][2], bv[1][3]);
            }
        }
        if (++st == NSTAGE) st = 0;
    }

#pragma unroll
    for (int mt = 0; mt < 2; mt++) {
        size_t row = (size_t)(m0 + wm + mt * 16 + g);
#pragma unroll
        for (int nt = 0; nt < 4; nt++) {
            size_t col = (size_t)(n0 + wn + nt * 8 + tg * 2);
            float2 v0 = make_float2(acc[mt][nt][0], acc[mt][nt][1]);
            float2 v1 = make_float2(acc[mt][nt][2], acc[mt][nt][3]);
            if (RES) {
                float2 r0 = *(const float2*)&Rsd[row * GN + col];
                float2 r1 = *(const float2*)&Rsd[(row + 8) * GN + col];
                v0.x += r0.x; v0.y += r0.y;
                v1.x += r1.x; v1.y += r1.y;
            }
            if (BF16OUT) {
                __nv_bfloat16* C = (__nv_bfloat16*)Cv;
                *(uint32_t*)&C[row * GN + col] = pack_bf2(v0.x, v0.y);
                *(uint32_t*)&C[(row + 8) * GN + col] = pack_bf2(v1.x, v1.y);
            } else {
                float* C = (float*)Cv;
                *(float2*)&C[row * GN + col] = v0;
                *(float2*)&C[(row + 8) * GN + col] = v1;
            }
        }
    }
}

struct Gemm3Args {
    const __nv_bfloat16* A[3];
    const __nv_bfloat16* W[3];
    __nv_bfloat16* C[3];
};

__global__ __launch_bounds__(256, 3) void gemm_proj(Gemm3Args ga)
{
    extern __shared__ float sm[];
    uint32_t smb = smem_u32(sm);
    const int z = blockIdx.z;
    gemm_body<false, true>(ga.A[z], ga.W[z], nullptr, ga.C[z], smb);
}

__global__ __launch_bounds__(256, 3) void gemm_fc(
    const __nv_bfloat16* __restrict__ A, const __nv_bfloat16* __restrict__ W,
    const float* __restrict__ Rsd, float* __restrict__ C)
{
    extern __shared__ float sm[];
    uint32_t smb = smem_u32(sm);
    gemm_body<true, false>(A, W, Rsd, C, smb);
}

// ------------------------------------------------------------------
// Flash attention, FA2-style, no online max, 3-stage K/V ring.
// (Proven R13 version: 1 tile/iter, MUFU ex2.)
// ------------------------------------------------------------------
#define FB_Q  0            // 128 x 144B = 18432
#define FB_K  18432        // 3 x 64 x 144B = 27648
#define FB_V  46080        // 3 x 64 x 144B = 27648
#define FB_ME 73728        // 3 x 256B
#define FB_SD 74496        // 3 x 256B
#define FLASH_SMEM_BYTES 75264

__device__ __forceinline__ void f_load_kv(
    uint32_t smb, int s, const __nv_bfloat16* __restrict__ Kp,
    const __nv_bfloat16* __restrict__ Vp,
    const float* __restrict__ meC, const float* __restrict__ sdC,
    int b, int h, int kt, int tid)
{
    const __nv_bfloat16* Kg = Kp + ((size_t)b * LKS + kt * 64) * DM + h * DKH;
    const __nv_bfloat16* Vg = Vp + ((size_t)b * LKS + kt * 64) * DM + h * DKH;
    uint32_t ks = smb + FB_K + s * 9216;
    uint32_t vs = smb + FB_V + s * 9216;
#pragma unroll
    for (int r = 0; r < 2; r++) {
        int idx = tid + r * 256;
        int row = idx >> 3, c4 = idx & 7;
        CP_ASYNC16(ks + row * 144 + c4 * 16, Kg + (size_t)row * DM + c4 * 8);
        CP_ASYNC16(vs + row * 144 + c4 * 16, Vg + (size_t)row * DM + c4 * 8);
    }
    if (tid < 16)
        CP_ASYNC16(smb + FB_ME + s * 256 + tid * 16, meC + (size_t)b * LKS + kt * 64 + tid * 4);
    else if (tid < 32)
        CP_ASYNC16(smb + FB_SD + s * 256 + (tid - 16) * 16, sdC + (size_t)b * LKS + kt * 64 + (tid - 16) * 4);
}

__global__ __launch_bounds__(256, 2) void flash_mma(
    const __nv_bfloat16* __restrict__ Qp, const __nv_bfloat16* __restrict__ Kp,
    const __nv_bfloat16* __restrict__ Vp, const uint32_t* __restrict__ mb,
    const float* __restrict__ meC, const float* __restrict__ sdC,
    __nv_bfloat16* __restrict__ Oout)
{
    extern __shared__ char smc[];
    uint32_t smb = smem_u32(smc);

    const int tid = threadIdx.x;
    const int wid = tid >> 5, lane = tid & 31;
    const int g = lane >> 2, tg = lane & 3;
    const int wm = wid * 16;
    const int b = blockIdx.z, h = blockIdx.y;
    const int q0 = blockIdx.x * 128;

    const int jr = lane & 7, jt = lane >> 3;
    const uint32_t aoff = (uint32_t)(((jt & 1) * 8 + jr) * 144 + (jt >> 1) * 16);
    const uint32_t qBase = smb + FB_Q + wm * 144 + aoff;

    const __nv_bfloat16* Qg = Qp + ((size_t)b * LQS + q0) * DM + h * DKH;
#pragma unroll
    for (int r = 0; r < 4; r++) {
        int idx = tid + r * 256;
        int row = idx >> 3, c4 = idx & 7;
        CP_ASYNC16(smb + FB_Q + row * 144 + c4 * 16, Qg + (size_t)row * DM + c4 * 8);
    }
    f_load_kv(smb, 0, Kp, Vp, meC, sdC, b, h, 0, tid);
    CP_COMMIT();
    f_load_kv(smb, 1, Kp, Vp, meC, sdC, b, h, 1, tid);
    CP_COMMIT();

    float oa[8][4];
#pragma unroll
    for (int nt = 0; nt < 8; nt++)
#pragma unroll
        for (int r = 0; r < 4; r++) oa[nt][r] = 0.f;

    float l0 = 0.f, l1 = 0.f;
    bool qf_loaded = false;
    uint32_t qf[4][4];

    const uint32_t* mrow0 = mb + ((size_t)b * LQS + q0 + wm + g) * (LKS / 32);
    const uint32_t* mrow1 = mrow0 + 8 * (LKS / 32);

    int st = 0;
    for (int i = 0; i < 32; i++) {
        CP_WAIT1();
        __syncthreads();

        {
            int ps = st + 2; if (ps >= 3) ps -= 3;
            if (i + 2 < 32) f_load_kv(smb, ps, Kp, Vp, meC, sdC, b, h, i + 2, tid);
            CP_COMMIT();
        }

        if (!qf_loaded) {
            qf_loaded = true;
#pragma unroll
            for (int ks = 0; ks < 4; ks++) ldsm_x4(qf[ks], qBase + ks * 32);
        }

        const uint32_t kB = smb + FB_K + st * 9216 + aoff;
        const uint32_t vB = smb + FB_V + st * 9216 + aoff;

        // ---- S = Q K^T ----
        float sa[8][4];
#pragma unroll
        for (int nt = 0; nt < 8; nt++)
#pragma unroll
            for (int r = 0; r < 4; r++) sa[nt][r] = 0.f;
#pragma unroll
        for (int ks = 0; ks < 4; ks++) {
            uint32_t bk[4][4];
#pragma unroll
            for (int t = 0; t < 4; t++)
                ldsm_x4(bk[t], kB + t * 2304 + ks * 32);
#pragma unroll
            for (int t = 0; t < 4; t++) {
                mma_bf16(sa[2 * t], qf[ks], bk[t][0], bk[t][2]);
                mma_bf16(sa[2 * t + 1], qf[ks], bk[t][1], bk[t][3]);
            }
        }

        // ---- softmax numerator (MUFU ex2) ----
        const float* meS = (const float*)(smc + FB_ME + st * 256);
        const float* sdS = (const float*)(smc + FB_SD + st * 256);
        const uint32_t mw0a = mrow0[i * 2], mw0b = mrow0[i * 2 + 1];
        const uint32_t mw1a = mrow1[i * 2], mw1b = mrow1[i * 2 + 1];

#pragma unroll
        for (int nt = 0; nt < 8; nt++) {
            float2 me = *(const float2*)&meS[nt * 8 + tg * 2];
            float2 sd = *(const float2*)&sdS[nt * 8 + tg * 2];
            float a0 = fmaf(sa[nt][0], me.x, sd.x);
            float a1 = fmaf(sa[nt][1], me.y, sd.y);
            float a2 = fmaf(sa[nt][2], me.x, sd.x);
            float a3 = fmaf(sa[nt][3], me.y, sd.y);
            const uint32_t w0 = (nt < 4) ? mw0a : mw0b;
            const uint32_t w1 = (nt < 4) ? mw1a : mw1b;
            const int sh = (nt & 3) * 8 + tg * 2;
            if (!((w0 >> sh) & 1))       a0 = -126.f;
            if (!((w0 >> (sh + 1)) & 1)) a1 = -126.f;
            if (!((w1 >> sh) & 1))       a2 = -126.f;
            if (!((w1 >> (sh + 1)) & 1)) a3 = -126.f;
            float p0 = ex2f(a0);
            float p1 = ex2f(a1);
            float p2 = ex2f(a2);
            float p3 = ex2f(a3);
            sa[nt][0] = p0; sa[nt][1] = p1; sa[nt][2] = p2; sa[nt][3] = p3;
            l0 += p0 + p1;
            l1 += p2 + p3;
        }

        // ---- O += P @ V ----
#pragma unroll
        for (int kk = 0; kk < 4; kk++) {
            uint32_t bv[4][4];
#pragma unroll
            for (int t = 0; t < 4; t++)
                ldsm_x4_t(bv[t], vB + kk * 2304 + t * 32);
            uint32_t pa[4];
            pa[0] = pack_bf2(sa[2 * kk][0], sa[2 * kk][1]);
            pa[1] = pack_bf2(sa[2 * kk][2], sa[2 * kk][3]);
            pa[2] = pack_bf2(sa[2 * kk + 1][0], sa[2 * kk + 1][1]);
            pa[3] = pack_bf2(sa[2 * kk + 1][2], sa[2 * kk + 1][3]);
#pragma unroll
            for (int t = 0; t < 4; t++) {
                mma_bf16(oa[2 * t], pa, bv[t][0], bv[t][1]);
                mma_bf16(oa[2 * t + 1], pa, bv[t][2], bv[t][3]);
            }
        }

        if (++st == 3) st = 0;
    }

    // ---- row-sum reduce + epilogue ----
    l0 += __shfl_xor_sync(0xffffffffu, l0, 1);
    l0 += __shfl_xor_sync(0xffffffffu, l0, 2);
    l1 += __shfl_xor_sync(0xffffffffu, l1, 1);
    l1 += __shfl_xor_sync(0xffffffffu, l1, 2);
    const float inv0 = __fdividef(1.f, l0);
    const float inv1 = __fdividef(1.f, l1);
    __nv_bfloat16* o0 = Oout + ((size_t)b * LQS + q0 + wm + g) * DM + h * DKH;
    __nv_bfloat16* o1 = o0 + 8 * DM;
#pragma unroll
    for (int nt = 0; nt < 8; nt++) {
        int col = nt * 8 + tg * 2;
        *(uint32_t*)&o0[col] = pack_bf2(oa[nt][0] * inv0, oa[nt][1] * inv0);
        *(uint32_t*)&o1[col] = pack_bf2(oa[nt][2] * inv1, oa[nt][3] * inv1);
    }
}

// ------------------------------------------------------------------
// LayerNorm over rows of 1024
// ------------------------------------------------------------------
__global__ __launch_bounds__(256) void ln_kernel(
    const float* __restrict__ X, const float* __restrict__ gamma,
    const float* __restrict__ beta, float* __restrict__ out)
{
    __shared__ float red[8];
    const int row = blockIdx.x, tid = threadIdx.x;
    const float* xr = X + (size_t)row * DM;
    float v[4];
    float s = 0.f;
#pragma unroll
    for (int j = 0; j < 4; j++) { v[j] = xr[tid + 256 * j]; s += v[j]; }
#pragma unroll
    for (int off = 16; off >= 1; off >>= 1) s += __shfl_xor_sync(0xffffffffu, s, off);
    if ((tid & 31) == 0) red[tid >> 5] = s;
    __syncthreads();
    float tot = 0.f;
#pragma unroll
    for (int w = 0; w < 8; w++) tot += red[w];
    float mu = tot * (1.f / DM);

    float s2 = 0.f;
#pragma unroll
    for (int j = 0; j < 4; j++) { float d = v[j] - mu; s2 += d * d; }
#pragma unroll
    for (int off = 16; off >= 1; off >>= 1) s2 += __shfl_xor_sync(0xffffffffu, s2, off);
    __syncthreads();
    if ((tid & 31) == 0) red[tid >> 5] = s2;
    __syncthreads();
    float tv = 0.f;
#pragma unroll
    for (int w = 0; w < 8; w++) tv += red[w];
    float inv = rsqrtf(tv * (1.f / DM) + 1e-6f);

#pragma unroll
    for (int j = 0; j < 4; j++) {
        int c = tid + 256 * j;
        out[(size_t)row * DM + c] = (v[j] - mu) * inv * gamma[c] + beta[c];
    }
}

// ------------------------------------------------------------------
// Launch
// ------------------------------------------------------------------
extern "C" void kernel_launch(void* const* d_in, const int* in_sizes, int n_in,
                              void* d_out, int out_size)
{
    (void)in_sizes; (void)n_in; (void)out_size;
    const float* q     = (const float*)d_in[0];
    const float* k     = (const float*)d_in[1];
    const float* v     = (const float*)d_in[2];
    const int*   mask  = (const int*)d_in[3];
    const float* mean  = (const float*)d_in[4];
    const float* stdv  = (const float*)d_in[5];
    const float* w_qs  = (const float*)d_in[6];
    const float* w_ks  = (const float*)d_in[7];
    const float* w_vs  = (const float*)d_in[8];
    const float* w_fc  = (const float*)d_in[9];
    const float* gamma = (const float*)d_in[10];
    const float* beta  = (const float*)d_in[11];
    float* out = (float*)d_out;

    void *pqb, *pkb, *pvb, *pwq, *pwk, *pwv, *pwf;
    void *pQ, *pK, *pV, *pA, *pF, *pM, *pMe, *pSd;
    cudaGetSymbolAddress(&pqb, g_qb);
    cudaGetSymbolAddress(&pkb, g_kb);
    cudaGetSymbolAddress(&pvb, g_vb);
    cudaGetSymbolAddress(&pwq, g_wqb);
    cudaGetSymbolAddress(&pwk, g_wkb);
    cudaGetSymbolAddress(&pwv, g_wvb);
    cudaGetSymbolAddress(&pwf, g_wfb);
    cudaGetSymbolAddress(&pQ, g_Qp);
    cudaGetSymbolAddress(&pK, g_Kp);
    cudaGetSymbolAddress(&pV, g_Vp);
    cudaGetSymbolAddress(&pA, g_attn);
    cudaGetSymbolAddress(&pF, g_fc);
    cudaGetSymbolAddress(&pM, g_mb);
    cudaGetSymbolAddress(&pMe, g_meC);
    cudaGetSymbolAddress(&pSd, g_sdC);
    __nv_bfloat16* qb = (__nv_bfloat16*)pqb;
    __nv_bfloat16* kb = (__nv_bfloat16*)pkb;
    __nv_bfloat16* vb = (__nv_bfloat16*)pvb;
    __nv_bfloat16* wqb = (__nv_bfloat16*)pwq;
    __nv_bfloat16* wkb = (__nv_bfloat16*)pwk;
    __nv_bfloat16* wvb = (__nv_bfloat16*)pwv;
    __nv_bfloat16* wfb = (__nv_bfloat16*)pwf;
    __nv_bfloat16* Qp = (__nv_bfloat16*)pQ;
    __nv_bfloat16* Kp = (__nv_bfloat16*)pK;
    __nv_bfloat16* Vp = (__nv_bfloat16*)pV;
    __nv_bfloat16* Ap = (__nv_bfloat16*)pA;
    float* Fp = (float*)pF;
    uint32_t* Mb = (uint32_t*)pM;
    float* MeC = (float*)pMe;
    float* SdC = (float*)pSd;

    cudaFuncSetAttribute(flash_mma, cudaFuncAttributeMaxDynamicSharedMemorySize,
                         FLASH_SMEM_BYTES);
    cudaFuncSetAttribute(gemm_proj, cudaFuncAttributeMaxDynamicSharedMemorySize, GSMEM);
    cudaFuncSetAttribute(gemm_fc, cudaFuncAttributeMaxDynamicSharedMemorySize, GSMEM);

    PrepArgs pa;
    pa.src[0] = (const float4*)q;    pa.dst[0] = (uint2*)qb;
    pa.src[1] = (const float4*)k;    pa.dst[1] = (uint2*)kb;
    pa.src[2] = (const float4*)v;    pa.dst[2] = (uint2*)vb;
    pa.src[3] = (const float4*)w_qs; pa.dst[3] = (uint2*)wqb;
    pa.src[4] = (const float4*)w_ks; pa.dst[4] = (uint2*)wkb;
    pa.src[5] = (const float4*)w_vs; pa.dst[5] = (uint2*)wvb;
    pa.src[6] = (const float4*)w_fc; pa.dst[6] = (uint2*)wfb;

    prep<<<1184, 256>>>(pa, mean, stdv, MeC, SdC, mask, Mb);

    Gemm3Args ga;
    ga.A[0] = qb; ga.W[0] = wqb; ga.C[0] = Qp;
    ga.A[1] = kb; ga.W[1] = wkb; ga.C[1] = Kp;
    ga.A[2] = vb; ga.W[2] = wvb; ga.C[2] = Vp;

    dim3 gg(GN / GBN, (BATCH * LQS) / GBM, 3);  // (8, 64, 3)
    gemm_proj<<<gg, 256, GSMEM>>>(ga);

    dim3 gf(LQS / 128, NHEAD, BATCH);  // (16, 16, 2)
    flash_mma<<<gf, 256, FLASH_SMEM_BYTES>>>(Qp, Kp, Vp, Mb, MeC, SdC, Ap);

    dim3 g2(GN / GBN, (BATCH * LQS) / GBM);  // (8, 64)
    gemm_fc<<<g2, 256, GSMEM>>>(Ap, wfb, q, Fp);

    ln_kernel<<<BATCH * LQS, 256>>>(Fp, gamma, beta, out);
}

// round 16
// speedup vs baseline: 1.0500x; 1.0500x over previous
#include <cuda_runtime.h>
#include <cuda_bf16.h>
#include <cstdint>

#define BATCH 2
#define LQS 2048
#define LKS 2048
#define DM 1024
#define NHEAD 16
#define DKH 64

// ------------------------------------------------------------------
// Scratch (device globals; no cudaMalloc allowed)
// ------------------------------------------------------------------
__device__ __nv_bfloat16 g_qb[BATCH * LQS * DM];
__device__ __nv_bfloat16 g_kb[BATCH * LKS * DM];
__device__ __nv_bfloat16 g_vb[BATCH * LKS * DM];
__device__ __nv_bfloat16 g_wqb[DM * DM];
__device__ __nv_bfloat16 g_wkb[DM * DM];
__device__ __nv_bfloat16 g_wvb[DM * DM];
__device__ __nv_bfloat16 g_wfb[DM * DM];
__device__ __nv_bfloat16 g_Qp[BATCH * LQS * DM];
__device__ __nv_bfloat16 g_Kp[BATCH * LKS * DM];
__device__ __nv_bfloat16 g_Vp[BATCH * LKS * DM];
__device__ __nv_bfloat16 g_attn[BATCH * LQS * DM];
__device__ float g_fc[BATCH * LQS * DM];
__device__ uint32_t g_mb[BATCH * LQS * (LKS / 32)];
__device__ float g_meC[BATCH * LKS];
__device__ float g_sdC[BATCH * LKS];

// ------------------------------------------------------------------
// PTX helpers
// ------------------------------------------------------------------
__device__ __forceinline__ void mma_bf16(float* c, const uint32_t* a, uint32_t b0, uint32_t b1) {
    asm volatile(
        "mma.sync.aligned.m16n8k16.row.col.f32.bf16.bf16.f32 "
        "{%0,%1,%2,%3}, {%4,%5,%6,%7}, {%8,%9}, {%0,%1,%2,%3};"
        : "+f"(c[0]), "+f"(c[1]), "+f"(c[2]), "+f"(c[3])
        : "r"(a[0]), "r"(a[1]), "r"(a[2]), "r"(a[3]), "r"(b0), "r"(b1));
}
__device__ __forceinline__ void ldsm_x4(uint32_t* r, uint32_t addr) {
    asm volatile(
        "ldmatrix.sync.aligned.m8n8.x4.shared.b16 {%0,%1,%2,%3}, [%4];"
        : "=r"(r[0]), "=r"(r[1]), "=r"(r[2]), "=r"(r[3]) : "r"(addr));
}
__device__ __forceinline__ void ldsm_x4_t(uint32_t* r, uint32_t addr) {
    asm volatile(
        "ldmatrix.sync.aligned.m8n8.x4.trans.shared.b16 {%0,%1,%2,%3}, [%4];"
        : "=r"(r[0]), "=r"(r[1]), "=r"(r[2]), "=r"(r[3]) : "r"(addr));
}

#define CP_ASYNC16(dst, src) \
    asm volatile("cp.async.cg.shared.global [%0], [%1], 16;" :: "r"(dst), "l"(src))
#define CP_COMMIT() asm volatile("cp.async.commit_group;" ::: "memory")
#define CP_WAIT2() asm volatile("cp.async.wait_group 2;" ::: "memory")
#define CP_WAIT1() asm volatile("cp.async.wait_group 1;" ::: "memory")
#define CP_WAIT0() asm volatile("cp.async.wait_group 0;" ::: "memory")

__device__ __forceinline__ uint32_t smem_u32(const void* p) {
    uint32_t a;
    asm("{ .reg .u64 t; cvta.to.shared.u64 t, %1; cvt.u32.u64 %0, t; }" : "=r"(a) : "l"(p));
    return a;
}
__device__ __forceinline__ uint32_t pack_bf2(float lo, float hi) {
    __nv_bfloat162 h = __floats2bfloat162_rn(lo, hi);
    return *(uint32_t*)&h;
}

// exp2 via MUFU.
__device__ __forceinline__ float ex2f(float y) {
    float r;
    asm("ex2.approx.f32 %0, %1;" : "=f"(r) : "f"(y));
    return r;
}

// ------------------------------------------------------------------
// Fused prep: 7 fp32->bf16 conversions + mean/std pre-scaling + mask pack
// ------------------------------------------------------------------
#define NIN4 ((BATCH * LQS * DM) / 4)   // 2^20
#define NW4 ((DM * DM) / 4)             // 2^18
struct PrepArgs {
    const float4* src[7];
    uint2* dst[7];
};

__global__ __launch_bounds__(256) void prep(
    PrepArgs pa, const float* __restrict__ mean, const float* __restrict__ stdv,
    float* __restrict__ meC, float* __restrict__ sdC,
    const int* __restrict__ mask, uint32_t* __restrict__ mb)
{
    const int TOT = 3 * NIN4 + 4 * NW4;
    const int stride = gridDim.x * blockDim.x;
    for (int i = blockIdx.x * blockDim.x + threadIdx.x; i < TOT; i += stride) {
        int seg, off;
        if (i < 3 * NIN4) { seg = i >> 20; off = i & (NIN4 - 1); }
        else { int j = i - 3 * NIN4; seg = 3 + (j >> 18); off = j & (NW4 - 1); }
        float4 v = pa.src[seg][off];
        uint2 u;
        u.x = pack_bf2(v.x, v.y);
        u.y = pack_bf2(v.z, v.w);
        pa.dst[seg][off] = u;
    }
    const float CAFF = 0.18033688011f;  // 0.125 * log2(e)
    for (int i = blockIdx.x * blockDim.x + threadIdx.x; i < BATCH * LKS; i += stride) {
        meC[i] = mean[i] * CAFF;
        sdC[i] = stdv[i] * CAFF;
    }
    const int nwords = BATCH * LQS * (LKS / 32);
    int warp = (blockIdx.x * blockDim.x + threadIdx.x) >> 5;
    int lane = threadIdx.x & 31;
    int wstep = stride >> 5;
    for (int w = warp; w < nwords; w += wstep) {
        int v = mask[(size_t)w * 32 + lane];
        uint32_t bits = __ballot_sync(0xffffffffu, v != 0);
        if (lane == 0) mb[w] = bits;
    }
}

// ------------------------------------------------------------------
// bf16 GEMM via mma.m16n8k16: CTA tile 64x128, 8 warps (2x4),
// warp tile 32x32, 4-stage cp.async, 3 CTAs/SM. (Proven R13 config.)
// ------------------------------------------------------------------
#define GBM 64
#define GBN 128
#define GBK 32
#define GK 1024
#define GN 1024
#define A_LDB 80
#define B_LDB 272
#define ASTG_B (GBM * A_LDB)     // 5120
#define BSTG_B (GBK * B_LDB)     // 8704
#define STG_B (ASTG_B + BSTG_B)  // 13824
#define NSTAGE 4
#define GSMEM (NSTAGE * STG_B)   // 55296
#define GNITER (GK / GBK)

__device__ __forceinline__ void g_load_stage(
    uint32_t smb, int s, const __nv_bfloat16* __restrict__ A,
    const __nv_bfloat16* __restrict__ W, int m0, int n0, int kc0, int tid)
{
    uint32_t as = smb + s * STG_B;
    uint32_t bs = as + ASTG_B;
    {
        int row = tid >> 2, c = tid & 3;
        CP_ASYNC16(as + row * A_LDB + c * 16,
                   A + (size_t)(m0 + row) * GK + kc0 + c * 8);
    }
#pragma unroll
    for (int r = 0; r < 2; r++) {
        int idx = tid + r * 256;
        int row = idx >> 4, c = idx & 15;
        CP_ASYNC16(bs + row * B_LDB + c * 16,
                   W + (size_t)(kc0 + row) * GN + n0 + c * 8);
    }
}

template <bool RES, bool BF16OUT>
__device__ __forceinline__ void gemm_body(
    const __nv_bfloat16* __restrict__ A, const __nv_bfloat16* __restrict__ W,
    const float* __restrict__ Rsd, void* __restrict__ Cv, uint32_t smb)
{
    const int tid = threadIdx.x;
    const int wid = tid >> 5, lane = tid & 31;
    const int g = lane >> 2, tg = lane & 3;
    const int wm = (wid >> 2) * 32, wn = (wid & 3) * 32;
    const int m0 = blockIdx.y * GBM, n0 = blockIdx.x * GBN;

    const int jr = lane & 7, jt = lane >> 3;
    const uint32_t aoff = (uint32_t)(((jt & 1) * 8 + jr) * A_LDB + (jt >> 1) * 16);
    const uint32_t boff = (uint32_t)(((jt & 1) * 8 + jr) * B_LDB + (jt >> 1) * 16);

    float acc[2][4][4];
#pragma unroll
    for (int mt = 0; mt < 2; mt++)
#pragma unroll
        for (int nt = 0; nt < 4; nt++)
#pragma unroll
            for (int r = 0; r < 4; r++) acc[mt][nt][r] = 0.f;

#pragma unroll
    for (int s = 0; s < 3; s++) {
        g_load_stage(smb, s, A, W, m0, n0, s * GBK, tid);
        CP_COMMIT();
    }

    for (int i = 0; i < GNITER; i++) {
        CP_WAIT2();
        __syncthreads();
        if (i + 3 < GNITER)
            g_load_stage(smb, (i + 3) & 3, A, W, m0, n0, (i + 3) * GBK, tid);
        CP_COMMIT();

        const int s = i & 3;
        const uint32_t aSt = smb + s * STG_B + wm * A_LDB + aoff;
        const uint32_t bSt = smb + s * STG_B + ASTG_B + wn * 2 + boff;

#pragma unroll
        for (int ks = 0; ks < 2; ks++) {
            uint32_t af[2][4], bv[2][4];
#pragma unroll
            for (int mt = 0; mt < 2; mt++)
                ldsm_x4(af[mt], aSt + mt * (16 * A_LDB) + ks * 32);
#pragma unroll
            for (int nh = 0; nh < 2; nh++)
                ldsm_x4_t(bv[nh], bSt + ks * (16 * B_LDB) + nh * 32);
#pragma unroll
            for (int mt = 0; mt < 2; mt++) {
                mma_bf16(acc[mt][0], af[mt], bv[0][0], bv[0][1]);
                mma_bf16(acc[mt][1], af[mt], bv[0][2], bv[0][3]);
                mma_bf16(acc[mt][2], af[mt], bv[1][0], bv[1][1]);
                mma_bf16(acc[mt][3], af[mt], bv[1][2], bv[1][3]);
            }
        }
    }

#pragma unroll
    for (int mt = 0; mt < 2; mt++) {
        size_t row = (size_t)(m0 + wm + mt * 16 + g);
#pragma unroll
        for (int nt = 0; nt < 4; nt++) {
            size_t col = (size_t)(n0 + wn + nt * 8 + tg * 2);
            float2 v0 = make_float2(acc[mt][nt][0], acc[mt][nt][1]);
            float2 v1 = make_float2(acc[mt][nt][2], acc[mt][nt][3]);
            if (RES) {
                float2 r0 = *(const float2*)&Rsd[row * GN + col];
                float2 r1 = *(const float2*)&Rsd[(row + 8) * GN + col];
                v0.x += r0.x; v0.y += r0.y;
                v1.x += r1.x; v1.y += r1.y;
            }
            if (BF16OUT) {
                __nv_bfloat16* C = (__nv_bfloat16*)Cv;
                *(uint32_t*)&C[row * GN + col] = pack_bf2(v0.x, v0.y);
                *(uint32_t*)&C[(row + 8) * GN + col] = pack_bf2(v1.x, v1.y);
            } else {
                float* C = (float*)Cv;
                *(float2*)&C[row * GN + col] = v0;
                *(float2*)&C[(row + 8) * GN + col] = v1;
            }
        }
    }
}

struct Gemm3Args {
    const __nv_bfloat16* A[3];
    const __nv_bfloat16* W[3];
    __nv_bfloat16* C[3];
};

__global__ __launch_bounds__(256, 3) void gemm_proj(Gemm3Args ga)
{
    extern __shared__ float sm[];
    uint32_t smb = smem_u32(sm);
    const int z = blockIdx.z;
    gemm_body<false, true>(ga.A[z], ga.W[z], nullptr, ga.C[z], smb);
}

__global__ __launch_bounds__(256, 3) void gemm_fc(
    const __nv_bfloat16* __restrict__ A, const __nv_bfloat16* __restrict__ W,
    const float* __restrict__ Rsd, float* __restrict__ C)
{
    extern __shared__ float sm[];
    uint32_t smb = smem_u32(sm);
    gemm_body<true, false>(A, W, Rsd, C, smb);
}

// ------------------------------------------------------------------
// Flash attention, FA2-style, no online max, 3-stage K/V ring.
// Mask words loaded at iteration top (latency hidden under QK mma).
// ------------------------------------------------------------------
#define FB_Q  0            // 128 x 144B = 18432
#define FB_K  18432        // 3 x 64 x 144B = 27648
#define FB_V  46080        // 3 x 64 x 144B = 27648
#define FB_ME 73728        // 3 x 256B
#define FB_SD 74496        // 3 x 256B
#define FLASH_SMEM_BYTES 75264

__device__ __forceinline__ void f_load_kv(
    uint32_t smb, int s, const __nv_bfloat16* __restrict__ Kp,
    const __nv_bfloat16* __restrict__ Vp,
    const float* __restrict__ meC, const float* __restrict__ sdC,
    int b, int h, int kt, int tid)
{
    const __nv_bfloat16* Kg = Kp + ((size_t)b * LKS + kt * 64) * DM + h * DKH;
    const __nv_bfloat16* Vg = Vp + ((size_t)b * LKS + kt * 64) * DM + h * DKH;
    uint32_t ks = smb + FB_K + s * 9216;
    uint32_t vs = smb + FB_V + s * 9216;
#pragma unroll
    for (int r = 0; r < 2; r++) {
        int idx = tid + r * 256;
        int row = idx >> 3, c4 = idx & 7;
        CP_ASYNC16(ks + row * 144 + c4 * 16, Kg + (size_t)row * DM + c4 * 8);
        CP_ASYNC16(vs + row * 144 + c4 * 16, Vg + (size_t)row * DM + c4 * 8);
    }
    if (tid < 16)
        CP_ASYNC16(smb + FB_ME + s * 256 + tid * 16, meC + (size_t)b * LKS + kt * 64 + tid * 4);
    else if (tid < 32)
        CP_ASYNC16(smb + FB_SD + s * 256 + (tid - 16) * 16, sdC + (size_t)b * LKS + kt * 64 + (tid - 16) * 4);
}

__global__ __launch_bounds__(256, 2) void flash_mma(
    const __nv_bfloat16* __restrict__ Qp, const __nv_bfloat16* __restrict__ Kp,
    const __nv_bfloat16* __restrict__ Vp, const uint32_t* __restrict__ mb,
    const float* __restrict__ meC, const float* __restrict__ sdC,
    __nv_bfloat16* __restrict__ Oout)
{
    extern __shared__ char smc[];
    uint32_t smb = smem_u32(smc);

    const int tid = threadIdx.x;
    const int wid = tid >> 5, lane = tid & 31;
    const int g = lane >> 2, tg = lane & 3;
    const int wm = wid * 16;
    const int b = blockIdx.z, h = blockIdx.y;
    const int q0 = blockIdx.x * 128;

    const int jr = lane & 7, jt = lane >> 3;
    const uint32_t aoff = (uint32_t)(((jt & 1) * 8 + jr) * 144 + (jt >> 1) * 16);
    const uint32_t qBase = smb + FB_Q + wm * 144 + aoff;

    const __nv_bfloat16* Qg = Qp + ((size_t)b * LQS + q0) * DM + h * DKH;
#pragma unroll
    for (int r = 0; r < 4; r++) {
        int idx = tid + r * 256;
        int row = idx >> 3, c4 = idx & 7;
        CP_ASYNC16(smb + FB_Q + row * 144 + c4 * 16, Qg + (size_t)row * DM + c4 * 8);
    }
    f_load_kv(smb, 0, Kp, Vp, meC, sdC, b, h, 0, tid);
    CP_COMMIT();
    f_load_kv(smb, 1, Kp, Vp, meC, sdC, b, h, 1, tid);
    CP_COMMIT();

    float oa[8][4];
#pragma unroll
    for (int nt = 0; nt < 8; nt++)
#pragma unroll
        for (int r = 0; r < 4; r++) oa[nt][r] = 0.f;

    float l0 = 0.f, l1 = 0.f;
    bool qf_loaded = false;
    uint32_t qf[4][4];

    const uint32_t* mrow0 = mb + ((size_t)b * LQS + q0 + wm + g) * (LKS / 32);
    const uint32_t* mrow1 = mrow0 + 8 * (LKS / 32);

    int st = 0;
    for (int i = 0; i < 32; i++) {
        CP_WAIT1();
        __syncthreads();

        // mask words for THIS tile — issued early, consumed after QK mma
        const uint32_t mw0a = mrow0[i * 2], mw0b = mrow0[i * 2 + 1];
        const uint32_t mw1a = mrow1[i * 2], mw1b = mrow1[i * 2 + 1];

        {
            int ps = st + 2; if (ps >= 3) ps -= 3;
            if (i + 2 < 32) f_load_kv(smb, ps, Kp, Vp, meC, sdC, b, h, i + 2, tid);
            CP_COMMIT();
        }

        if (!qf_loaded) {
            qf_loaded = true;
#pragma unroll
            for (int ks = 0; ks < 4; ks++) ldsm_x4(qf[ks], qBase + ks * 32);
        }

        const uint32_t kB = smb + FB_K + st * 9216 + aoff;
        const uint32_t vB = smb + FB_V + st * 9216 + aoff;

        // ---- S = Q K^T ----
        float sa[8][4];
#pragma unroll
        for (int nt = 0; nt < 8; nt++)
#pragma unroll
            for (int r = 0; r < 4; r++) sa[nt][r] = 0.f;
#pragma unroll
        for (int ks = 0; ks < 4; ks++) {
            uint32_t bk[4][4];
#pragma unroll
            for (int t = 0; t < 4; t++)
                ldsm_x4(bk[t], kB + t * 2304 + ks * 32);
#pragma unroll
            for (int t = 0; t < 4; t++) {
                mma_bf16(sa[2 * t], qf[ks], bk[t][0], bk[t][2]);
                mma_bf16(sa[2 * t + 1], qf[ks], bk[t][1], bk[t][3]);
            }
        }

        // ---- softmax numerator (MUFU ex2) ----
        const float* meS = (const float*)(smc + FB_ME + st * 256);
        const float* sdS = (const float*)(smc + FB_SD + st * 256);

#pragma unroll
        for (int nt = 0; nt < 8; nt++) {
            float2 me = *(const float2*)&meS[nt * 8 + tg * 2];
            float2 sd = *(const float2*)&sdS[nt * 8 + tg * 2];
            float a0 = fmaf(sa[nt][0], me.x, sd.x);
            float a1 = fmaf(sa[nt][1], me.y, sd.y);
            float a2 = fmaf(sa[nt][2], me.x, sd.x);
            float a3 = fmaf(sa[nt][3], me.y, sd.y);
            const uint32_t w0 = (nt < 4) ? mw0a : mw0b;
            const uint32_t w1 = (nt < 4) ? mw1a : mw1b;
            const int sh = (nt & 3) * 8 + tg * 2;
            if (!((w0 >> sh) & 1))       a0 = -126.f;
            if (!((w0 >> (sh + 1)) & 1)) a1 = -126.f;
            if (!((w1 >> sh) & 1))       a2 = -126.f;
            if (!((w1 >> (sh + 1)) & 1)) a3 = -126.f;
            float p0 = ex2f(a0);
            float p1 = ex2f(a1);
            float p2 = ex2f(a2);
            float p3 = ex2f(a3);
            sa[nt][0] = p0; sa[nt][1] = p1; sa[nt][2] = p2; sa[nt][3] = p3;
            l0 += p0 + p1;
            l1 += p2 + p3;
        }

        // ---- O += P @ V ----
#pragma unroll
        for (int kk = 0; kk < 4; kk++) {
            uint32_t bv[4][4];
#pragma unroll
            for (int t = 0; t < 4; t++)
                ldsm_x4_t(bv[t], vB + kk * 2304 + t * 32);
            uint32_t pa[4];
            pa[0] = pack_bf2(sa[2 * kk][0], sa[2 * kk][1]);
            pa[1] = pack_bf2(sa[2 * kk][2], sa[2 * kk][3]);
            pa[2] = pack_bf2(sa[2 * kk + 1][0], sa[2 * kk + 1][1]);
            pa[3] = pack_bf2(sa[2 * kk + 1][2], sa[2 * kk + 1][3]);
#pragma unroll
            for (int t = 0; t < 4; t++) {
                mma_bf16(oa[2 * t], pa, bv[t][0], bv[t][1]);
                mma_bf16(oa[2 * t + 1], pa, bv[t][2], bv[t][3]);
            }
        }

        if (++st == 3) st = 0;
    }

    // ---- row-sum reduce + epilogue ----
    l0 += __shfl_xor_sync(0xffffffffu, l0, 1);
    l0 += __shfl_xor_sync(0xffffffffu, l0, 2);
    l1 += __shfl_xor_sync(0xffffffffu, l1, 1);
    l1 += __shfl_xor_sync(0xffffffffu, l1, 2);
    const float inv0 = __fdividef(1.f, l0);
    const float inv1 = __fdividef(1.f, l1);
    __nv_bfloat16* o0 = Oout + ((size_t)b * LQS + q0 + wm + g) * DM + h * DKH;
    __nv_bfloat16* o1 = o0 + 8 * DM;
#pragma unroll
    for (int nt = 0; nt < 8; nt++) {
        int col = nt * 8 + tg * 2;
        *(uint32_t*)&o0[col] = pack_bf2(oa[nt][0] * inv0, oa[nt][1] * inv0);
        *(uint32_t*)&o1[col] = pack_bf2(oa[nt][2] * inv1, oa[nt][3] * inv1);
    }
}

// ------------------------------------------------------------------
// LayerNorm over rows of 1024
// ------------------------------------------------------------------
__global__ __launch_bounds__(256) void ln_kernel(
    const float* __restrict__ X, const float* __restrict__ gamma,
    const float* __restrict__ beta, float* __restrict__ out)
{
    __shared__ float red[8];
    const int row = blockIdx.x, tid = threadIdx.x;
    const float* xr = X + (size_t)row * DM;
    float v[4];
    float s = 0.f;
#pragma unroll
    for (int j = 0; j < 4; j++) { v[j] = xr[tid + 256 * j]; s += v[j]; }
#pragma unroll
    for (int off = 16; off >= 1; off >>= 1) s += __shfl_xor_sync(0xffffffffu, s, off);
    if ((tid & 31) == 0) red[tid >> 5] = s;
    __syncthreads();
    float tot = 0.f;
#pragma unroll
    for (int w = 0; w < 8; w++) tot += red[w];
    float mu = tot * (1.f / DM);

    float s2 = 0.f;
#pragma unroll
    for (int j = 0; j < 4; j++) { float d = v[j] - mu; s2 += d * d; }
#pragma unroll
    for (int off = 16; off >= 1; off >>= 1) s2 += __shfl_xor_sync(0xffffffffu, s2, off);
    __syncthreads();
    if ((tid & 31) == 0) red[tid >> 5] = s2;
    __syncthreads();
    float tv = 0.f;
#pragma unroll
    for (int w = 0; w < 8; w++) tv += red[w];
    float inv = rsqrtf(tv * (1.f / DM) + 1e-6f);

#pragma unroll
    for (int j = 0; j < 4; j++) {
        int c = tid + 256 * j;
        out[(size_t)row * DM + c] = (v[j] - mu) * inv * gamma[c] + beta[c];
    }
}

// ------------------------------------------------------------------
// Launch
// ------------------------------------------------------------------
extern "C" void kernel_launch(void* const* d_in, const int* in_sizes, int n_in,
                              void* d_out, int out_size)
{
    (void)in_sizes; (void)n_in; (void)out_size;
    const float* q     = (const float*)d_in[0];
    const float* k     = (const float*)d_in[1];
    const float* v     = (const float*)d_in[2];
    const int*   mask  = (const int*)d_in[3];
    const float* mean  = (const float*)d_in[4];
    const float* stdv  = (const float*)d_in[5];
    const float* w_qs  = (const float*)d_in[6];
    const float* w_ks  = (const float*)d_in[7];
    const float* w_vs  = (const float*)d_in[8];
    const float* w_fc  = (const float*)d_in[9];
    const float* gamma = (const float*)d_in[10];
    const float* beta  = (const float*)d_in[11];
    float* out = (float*)d_out;

    void *pqb, *pkb, *pvb, *pwq, *pwk, *pwv, *pwf;
    void *pQ, *pK, *pV, *pA, *pF, *pM, *pMe, *pSd;
    cudaGetSymbolAddress(&pqb, g_qb);
    cudaGetSymbolAddress(&pkb, g_kb);
    cudaGetSymbolAddress(&pvb, g_vb);
    cudaGetSymbolAddress(&pwq, g_wqb);
    cudaGetSymbolAddress(&pwk, g_wkb);
    cudaGetSymbolAddress(&pwv, g_wvb);
    cudaGetSymbolAddress(&pwf, g_wfb);
    cudaGetSymbolAddress(&pQ, g_Qp);
    cudaGetSymbolAddress(&pK, g_Kp);
    cudaGetSymbolAddress(&pV, g_Vp);
    cudaGetSymbolAddress(&pA, g_attn);
    cudaGetSymbolAddress(&pF, g_fc);
    cudaGetSymbolAddress(&pM, g_mb);
    cudaGetSymbolAddress(&pMe, g_meC);
    cudaGetSymbolAddress(&pSd, g_sdC);
    __nv_bfloat16* qb = (__nv_bfloat16*)pqb;
    __nv_bfloat16* kb = (__nv_bfloat16*)pkb;
    __nv_bfloat16* vb = (__nv_bfloat16*)pvb;
    __nv_bfloat16* wqb = (__nv_bfloat16*)pwq;
    __nv_bfloat16* wkb = (__nv_bfloat16*)pwk;
    __nv_bfloat16* wvb = (__nv_bfloat16*)pwv;
    __nv_bfloat16* wfb = (__nv_bfloat16*)pwf;
    __nv_bfloat16* Qp = (__nv_bfloat16*)pQ;
    __nv_bfloat16* Kp = (__nv_bfloat16*)pK;
    __nv_bfloat16* Vp = (__nv_bfloat16*)pV;
    __nv_bfloat16* Ap = (__nv_bfloat16*)pA;
    float* Fp = (float*)pF;
    uint32_t* Mb = (uint32_t*)pM;
    float* MeC = (float*)pMe;
    float* SdC = (float*)pSd;

    cudaFuncSetAttribute(flash_mma, cudaFuncAttributeMaxDynamicSharedMemorySize,
                         FLASH_SMEM_BYTES);
    cudaFuncSetAttribute(gemm_proj, cudaFuncAttributeMaxDynamicSharedMemorySize, GSMEM);
    cudaFuncSetAttribute(gemm_fc, cudaFuncAttributeMaxDynamicSharedMemorySize, GSMEM);

    PrepArgs pa;
    pa.src[0] = (const float4*)q;    pa.dst[0] = (uint2*)qb;
    pa.src[1] = (const float4*)k;    pa.dst[1] = (uint2*)kb;
    pa.src[2] = (const float4*)v;    pa.dst[2] = (uint2*)vb;
    pa.src[3] = (const float4*)w_qs; pa.dst[3] = (uint2*)wqb;
    pa.src[4] = (const float4*)w_ks; pa.dst[4] = (uint2*)wkb;
    pa.src[5] = (const float4*)w_vs; pa.dst[5] = (uint2*)wvb;
    pa.src[6] = (const float4*)w_fc; pa.dst[6] = (uint2*)wfb;

    prep<<<1184, 256>>>(pa, mean, stdv, MeC, SdC, mask, Mb);

    Gemm3Args ga;
    ga.A[0] = qb; ga.W[0] = wqb; ga.C[0] = Qp;
    ga.A[1] = kb; ga.W[1] = wkb; ga.C[1] = Kp;
    ga.A[2] = vb; ga.W[2] = wvb; ga.C[2] = Vp;

    dim3 gg(GN / GBN, (BATCH * LQS) / GBM, 3);  // (8, 64, 3)
    gemm_proj<<<gg, 256, GSMEM>>>(ga);

    dim3 gf(LQS / 128, NHEAD, BATCH);  // (16, 16, 2)
    flash_mma<<<gf, 256, FLASH_SMEM_BYTES>>>(Qp, Kp, Vp, Mb, MeC, SdC, Ap);

    dim3 g2(GN / GBN, (BATCH * LQS) / GBM);  // (8, 64)
    gemm_fc<<<g2, 256, GSMEM>>>(Ap, wfb, q, Fp);

    ln_kernel<<<BATCH * LQS, 256>>>(Fp, gamma, beta, out);
}